// round 9
// baseline (speedup 1.0000x reference)
#include <cuda_runtime.h>
#include <cuda_fp16.h>
#include <cstdint>

// Problem constants
#define BATCH 16
#define NN    1024
#define FF    128
#define GTOT  (BATCH * NN)     // 16384

// ---------------------------------------------------------------------------
// Device-global scratch (no allocations allowed)
// ---------------------------------------------------------------------------
__device__ float  g_dinv[GTOT];             // 64 KB
__device__ __half g_Ah[(size_t)GTOT * NN];  // 32 MB  A in fp16, natural layout
__device__ __half g_YsT_h[FF * GTOT];       // 4 MB   [f][g] fp16, d_m-scaled
__device__ float  g_Ysn[GTOT * FF];         // 8 MB   [g][f] fp32, d_m-scaled

// ---------------------------------------------------------------------------
// Helpers
// ---------------------------------------------------------------------------
__device__ __forceinline__ uint32_t smem_to_u32(const void* p) {
    uint32_t a;
    asm("{ .reg .u64 t; cvta.to.shared.u64 t, %1; cvt.u32.u64 %0, t; }" : "=r"(a) : "l"(p));
    return a;
}
#define CP_ASYNC_16(dst_u32, src) \
    asm volatile("cp.async.cg.shared.global [%0], [%1], 16;" \
                 :: "r"(dst_u32), "l"(src) : "memory")
#define CP_ASYNC_COMMIT()  asm volatile("cp.async.commit_group;" ::: "memory")
#define CP_ASYNC_WAIT1()   asm volatile("cp.async.wait_group 1;" ::: "memory")
#define CP_ASYNC_WAIT0()   asm volatile("cp.async.wait_group 0;" ::: "memory")

#define LDSM_X4(r0, r1, r2, r3, addr) \
    asm volatile("ldmatrix.sync.aligned.m8n8.x4.shared.b16 {%0,%1,%2,%3}, [%4];" \
                 : "=r"(r0), "=r"(r1), "=r"(r2), "=r"(r3) : "r"(addr))

__device__ __forceinline__ void mma_f16(float* c, const uint32_t* a, const uint32_t* b) {
    asm volatile(
        "mma.sync.aligned.m16n8k16.row.col.f32.f16.f16.f32 "
        "{%0,%1,%2,%3}, {%4,%5,%6,%7}, {%8,%9}, {%0,%1,%2,%3};\n"
        : "+f"(c[0]), "+f"(c[1]), "+f"(c[2]), "+f"(c[3])
        : "r"(a[0]), "r"(a[1]), "r"(a[2]), "r"(a[3]), "r"(b[0]), "r"(b[1]));
}
__device__ __forceinline__ uint32_t pack_h2(float x, float y) {
    __half2 h = __floats2half2_rn(x, y);
    return reinterpret_cast<uint32_t&>(h);
}

// ---------------------------------------------------------------------------
// Kernel 1: dinv[row] = rsqrt(rowsum(A)+1)  AND  g_Ah = fp16(A)  (fused)
// ---------------------------------------------------------------------------
__global__ void __launch_bounds__(256) deg_kernel(const float* __restrict__ A) {
    const int wid = threadIdx.x >> 5, lid = threadIdx.x & 31;
    const int row0 = blockIdx.x * 16 + wid * 2;
    const float4* r0 = reinterpret_cast<const float4*>(A + (size_t)row0 * NN);
    const float4* r1 = reinterpret_cast<const float4*>(A + (size_t)(row0 + 1) * NN);
    __half* h0 = g_Ah + (size_t)row0 * NN;
    __half* h1 = h0 + NN;
    float s0 = 0.f, s1 = 0.f;
    #pragma unroll
    for (int i = 0; i < 8; i++) {
        float4 a = r0[lid + i * 32];
        float4 b = r1[lid + i * 32];
        s0 += (a.x + a.y) + (a.z + a.w);
        s1 += (b.x + b.y) + (b.z + b.w);
        uint2 pa = make_uint2(pack_h2(a.x, a.y), pack_h2(a.z, a.w));
        uint2 pb = make_uint2(pack_h2(b.x, b.y), pack_h2(b.z, b.w));
        *reinterpret_cast<uint2*>(h0 + (lid + i * 32) * 4) = pa;
        *reinterpret_cast<uint2*>(h1 + (lid + i * 32) * 4) = pb;
    }
    #pragma unroll
    for (int o = 16; o; o >>= 1) {
        s0 += __shfl_xor_sync(0xFFFFFFFFu, s0, o);
        s1 += __shfl_xor_sync(0xFFFFFFFFu, s1, o);
    }
    if (lid == 0) {
        g_dinv[row0]     = rsqrtf(s0 + 1.0f);
        g_dinv[row0 + 1] = rsqrtf(s1 + 1.0f);
    }
}

// ---------------------------------------------------------------------------
// Kernel 2: Ysd = d_m * (X @ W) via fp16 mma.sync, dual-layout output.
// ---------------------------------------------------------------------------
#define P2 272
#define XS_SZ (128 * P2)
#define SMEM2 (2 * XS_SZ)

__global__ void __launch_bounds__(256) gemm_xw_t(const float* __restrict__ X,
                                                 const float* __restrict__ W) {
    extern __shared__ char sm2[];
    char* Xs = sm2;
    char* Ws = sm2 + XS_SZ;

    const int tid = threadIdx.x;
    const int wid = tid >> 5, lane = tid & 31;
    const int g = lane >> 2, tig = lane & 3;
    const int wm = wid & 1, wn = wid >> 1;
    const int m0g = blockIdx.x * 128;

    for (int idx = tid; idx < 128 * 128; idx += 256) {
        int k = idx >> 7, f = idx & 127;
        float w = W[idx];
        *reinterpret_cast<__half*>(Ws + f * P2 + k * 2) = __float2half_rn(w);
    }
    {
        const int r = tid >> 1, half = tid & 1;
        const float* xp = X + (size_t)(m0g + r) * FF + half * 64;
        char* dst = Xs + r * P2 + half * 128;
        #pragma unroll
        for (int j = 0; j < 8; j++) {
            float4 v0 = *reinterpret_cast<const float4*>(xp + j * 8);
            float4 v1 = *reinterpret_cast<const float4*>(xp + j * 8 + 4);
            uint4 o;
            o.x = pack_h2(v0.x, v0.y); o.y = pack_h2(v0.z, v0.w);
            o.z = pack_h2(v1.x, v1.y); o.w = pack_h2(v1.z, v1.w);
            *reinterpret_cast<uint4*>(dst + j * 16) = o;
        }
    }
    __syncthreads();

    float acc[4][4][4];
    #pragma unroll
    for (int i = 0; i < 4; i++)
        #pragma unroll
        for (int j = 0; j < 4; j++)
            #pragma unroll
            for (int k = 0; k < 4; k++) acc[i][j][k] = 0.f;

    #pragma unroll
    for (int ks = 0; ks < 8; ks++) {
        const int kb = ks * 32 + tig * 4;
        uint32_t af[4][4], bf2[4][2];
        #pragma unroll
        for (int mt = 0; mt < 4; mt++) {
            char* p = Xs + (wm * 64 + mt * 16 + g) * P2 + kb;
            af[mt][0] = *reinterpret_cast<uint32_t*>(p);
            af[mt][1] = *reinterpret_cast<uint32_t*>(p + 8 * P2);
            af[mt][2] = *reinterpret_cast<uint32_t*>(p + 16);
            af[mt][3] = *reinterpret_cast<uint32_t*>(p + 8 * P2 + 16);
        }
        #pragma unroll
        for (int nt = 0; nt < 4; nt++) {
            char* p = Ws + (wn * 32 + nt * 8 + g) * P2 + kb;
            bf2[nt][0] = *reinterpret_cast<uint32_t*>(p);
            bf2[nt][1] = *reinterpret_cast<uint32_t*>(p + 16);
        }
        #pragma unroll
        for (int mt = 0; mt < 4; mt++)
            #pragma unroll
            for (int nt = 0; nt < 4; nt++)
                mma_f16(acc[mt][nt], af[mt], bf2[nt]);
    }
    __syncthreads();

    char* Os = Xs;
    #pragma unroll
    for (int mt = 0; mt < 4; mt++) {
        const int gl0 = wm * 64 + mt * 16 + g;
        const int gg0 = m0g + gl0;
        const float d0 = g_dinv[gg0];
        const float d1 = g_dinv[gg0 + 8];
        #pragma unroll
        for (int nt = 0; nt < 4; nt++) {
            const int f = wn * 32 + nt * 8 + tig * 2;
            float c0 = acc[mt][nt][0] * d0, c1 = acc[mt][nt][1] * d0;
            float c2 = acc[mt][nt][2] * d1, c3 = acc[mt][nt][3] * d1;
            *reinterpret_cast<float2*>(&g_Ysn[(size_t)gg0 * FF + f]) = make_float2(c0, c1);
            *reinterpret_cast<float2*>(&g_Ysn[(size_t)(gg0 + 8) * FF + f]) = make_float2(c2, c3);
            *reinterpret_cast<__half*>(Os + f * P2 + gl0 * 2)             = __float2half_rn(c0);
            *reinterpret_cast<__half*>(Os + (f + 1) * P2 + gl0 * 2)       = __float2half_rn(c1);
            *reinterpret_cast<__half*>(Os + f * P2 + (gl0 + 8) * 2)       = __float2half_rn(c2);
            *reinterpret_cast<__half*>(Os + (f + 1) * P2 + (gl0 + 8) * 2) = __float2half_rn(c3);
        }
    }
    __syncthreads();
    {
        const int f = tid >> 1, half = tid & 1;
        char* src = Os + f * P2 + half * 128;
        __half* dst = g_YsT_h + (size_t)f * GTOT + m0g + half * 64;
        #pragma unroll
        for (int j = 0; j < 8; j++)
            *reinterpret_cast<uint4*>(dst + j * 8) = *reinterpret_cast<uint4*>(src + j * 16);
    }
}

// ---------------------------------------------------------------------------
// Kernel 3: out[b,n,:] = d_n * ( A[b,n,:] @ Ysd[b] + Ysd[b,n,:] )
//   CTA tile 64(m) x 128(n), K-chunk 64, 3-stage cp.async, ldmatrix + fp16 MMA.
//   grid (16,16) = 256 CTAs, 128 threads (4 warps = 2m x 2n, warp tile 32x64).
// ---------------------------------------------------------------------------
#define PA3 144                     // 64 fp16 = 128B + 16B pad
#define TA3 (64 * PA3)              // 9216   (A tile: 64 rows)
#define TB3 (128 * PA3)             // 18432  (B tile: 128 rows)
#define STG3 (TA3 + TB3)            // 27648
#define NSTAGE 3
#define SMEM3 (NSTAGE * STG3)       // 82944
#define NCHUNK (NN / 64)            // 16

__global__ void __launch_bounds__(128, 2) gemm_mma(float* __restrict__ out) {
    extern __shared__ char sm[];
    const uint32_t sb = smem_to_u32(sm);

    const int tid = threadIdx.x;
    const int wid = tid >> 5, lane = tid & 31;
    const int g = lane >> 2, tig = lane & 3;
    const int wm = wid & 1, wn = wid >> 1;           // 2 x 2 warps
    const int b = blockIdx.y;
    const int rowStart = blockIdx.x * 64;

    // cp.async mapping
    const int ar = tid >> 1, ah = tid & 1;           // A: 64 rows, 64B halves
    const __half* Ap = g_Ah + ((size_t)b * NN + rowStart + ar) * NN + ah * 32;
    const __half* Bp = g_YsT_h + (size_t)tid * GTOT + (size_t)b * NN;  // B: row = tid
    const uint32_t dA0 = sb + ar * PA3 + ah * 64;
    const uint32_t dB0 = sb + TA3 + tid * PA3;

    auto issue = [&](int kc) {
        const uint32_t s = (kc % NSTAGE) * STG3;
        const __half* pa = Ap + kc * 64;
        const __half* pb = Bp + kc * 64;
        #pragma unroll
        for (int j = 0; j < 4; j++) CP_ASYNC_16(dA0 + s + j * 16, pa + j * 8);
        #pragma unroll
        for (int j = 0; j < 8; j++) CP_ASYNC_16(dB0 + s + j * 16, pb + j * 8);
        CP_ASYNC_COMMIT();
    };

    // ldmatrix lane addressing
    const int t = lane >> 3, r8 = lane & 7;
    // A x4 tiles: (m0,k0),(m0+8,k0),(m0,k0+8),(m0+8,k0+8)
    const uint32_t aOff = (uint32_t)(wm * 32 + (t & 1) * 8 + r8) * PA3 + ((t >> 1) * 8) * 2;
    // B x4 tiles (n-pair): (n0,k0),(n0,k0+8),(n0+8,k0),(n0+8,k0+8)
    const uint32_t bOff = TA3 + (uint32_t)(wn * 64 + (t >> 1) * 8 + r8) * PA3 + ((t & 1) * 8) * 2;

    float acc[2][8][4];
    #pragma unroll
    for (int i = 0; i < 2; i++)
        #pragma unroll
        for (int j = 0; j < 8; j++)
            #pragma unroll
            for (int k = 0; k < 4; k++) acc[i][j][k] = 0.f;

    issue(0);
    issue(1);

    for (int kc = 0; kc < NCHUNK; kc++) {
        if (kc < NCHUNK - 1) { CP_ASYNC_WAIT1(); } else { CP_ASYNC_WAIT0(); }
        __syncthreads();
        if (kc + 2 < NCHUNK) issue(kc + 2);

        const uint32_t st = sb + (kc % NSTAGE) * STG3;

        #pragma unroll
        for (int ks = 0; ks < 4; ks++) {
            uint32_t af[2][4], bf2[8][2];
            #pragma unroll
            for (int mt = 0; mt < 2; mt++)
                LDSM_X4(af[mt][0], af[mt][1], af[mt][2], af[mt][3],
                        st + aOff + (uint32_t)mt * 16 * PA3 + ks * 32);
            #pragma unroll
            for (int np = 0; np < 4; np++)
                LDSM_X4(bf2[np * 2][0], bf2[np * 2][1], bf2[np * 2 + 1][0], bf2[np * 2 + 1][1],
                        st + bOff + (uint32_t)np * 16 * PA3 + ks * 32);
            #pragma unroll
            for (int mt = 0; mt < 2; mt++)
                #pragma unroll
                for (int nt = 0; nt < 8; nt++)
                    mma_f16(acc[mt][nt], af[mt], bf2[nt]);
        }
    }

    // Epilogue: out = d_n * (acc + Ysd[n,:])  — identity term exact in fp32
    #pragma unroll
    for (int mt = 0; mt < 2; mt++) {
        const int gr0 = b * NN + rowStart + wm * 32 + mt * 16 + g;
        const float d0 = g_dinv[gr0];
        const float d1 = g_dinv[gr0 + 8];
        const float* ys0 = g_Ysn + (size_t)gr0 * FF + wn * 64 + tig * 2;
        const float* ys1 = ys0 + (size_t)8 * FF;
        float* o0 = out + (size_t)gr0 * FF + wn * 64 + tig * 2;
        float* o1 = o0 + (size_t)8 * FF;
        #pragma unroll
        for (int nt = 0; nt < 8; nt++) {
            float2 y0 = *reinterpret_cast<const float2*>(ys0 + nt * 8);
            float2 y1 = *reinterpret_cast<const float2*>(ys1 + nt * 8);
            float2 v0, v1;
            v0.x = d0 * (acc[mt][nt][0] + y0.x);
            v0.y = d0 * (acc[mt][nt][1] + y0.y);
            v1.x = d1 * (acc[mt][nt][2] + y1.x);
            v1.y = d1 * (acc[mt][nt][3] + y1.y);
            *reinterpret_cast<float2*>(o0 + nt * 8) = v0;
            *reinterpret_cast<float2*>(o1 + nt * 8) = v1;
        }
    }
}

// ---------------------------------------------------------------------------
// kernel_launch
// ---------------------------------------------------------------------------
extern "C" void kernel_launch(void* const* d_in, const int* in_sizes, int n_in,
                              void* d_out, int out_size) {
    const float* X = (const float*)d_in[0];   // [16,1024,128]
    const float* A = (const float*)d_in[1];   // [16,1024,1024]
    const float* W = (const float*)d_in[2];   // [128,128]
    float* out = (float*)d_out;               // [16,1024,128]

    cudaFuncSetAttribute(gemm_xw_t, cudaFuncAttributeMaxDynamicSharedMemorySize, SMEM2);
    cudaFuncSetAttribute(gemm_mma, cudaFuncAttributeMaxDynamicSharedMemorySize, SMEM3);

    // 1) dinv = rsqrt(rowsum(A)+1)  +  A -> fp16 (fused)
    deg_kernel<<<GTOT / 16, 256>>>(A);

    // 2) Ysd = d_m * (X @ W) via fp16 MMA, dual layout
    gemm_xw_t<<<GTOT / 128, 256, SMEM2>>>(X, W);

    // 3) out = d_n * (A @ Ysd + Ysd[n,:])  via ldmatrix + fp16 mma.sync
    {
        dim3 grid(NN / 64, BATCH);
        gemm_mma<<<grid, 128, SMEM3>>>(out);
    }
}

// round 10
// speedup vs baseline: 1.0983x; 1.0983x over previous
#include <cuda_runtime.h>
#include <cuda_fp16.h>
#include <cstdint>

// Problem constants
#define BATCH 16
#define NN    1024
#define FF    128
#define GTOT  (BATCH * NN)     // 16384

// ---------------------------------------------------------------------------
// Device-global scratch (no allocations allowed)
// ---------------------------------------------------------------------------
__device__ float  g_dinv[GTOT];             // 64 KB
__device__ __half g_Ah[(size_t)GTOT * NN];  // 32 MB  (A + I) in fp16, natural layout
__device__ __half g_YsT_h[FF * GTOT];       // 4 MB   [f][g] fp16, d_m-scaled

// ---------------------------------------------------------------------------
// Helpers
// ---------------------------------------------------------------------------
__device__ __forceinline__ uint32_t smem_to_u32(const void* p) {
    uint32_t a;
    asm("{ .reg .u64 t; cvta.to.shared.u64 t, %1; cvt.u32.u64 %0, t; }" : "=r"(a) : "l"(p));
    return a;
}
#define CP_ASYNC_16(dst_u32, src) \
    asm volatile("cp.async.cg.shared.global [%0], [%1], 16;" \
                 :: "r"(dst_u32), "l"(src) : "memory")
#define CP_ASYNC_COMMIT()  asm volatile("cp.async.commit_group;" ::: "memory")
#define CP_ASYNC_WAIT1()   asm volatile("cp.async.wait_group 1;" ::: "memory")
#define CP_ASYNC_WAIT0()   asm volatile("cp.async.wait_group 0;" ::: "memory")

#define LDSM_X4(r0, r1, r2, r3, addr) \
    asm volatile("ldmatrix.sync.aligned.m8n8.x4.shared.b16 {%0,%1,%2,%3}, [%4];" \
                 : "=r"(r0), "=r"(r1), "=r"(r2), "=r"(r3) : "r"(addr))

__device__ __forceinline__ void mma_f16(float* c, const uint32_t* a, const uint32_t* b) {
    asm volatile(
        "mma.sync.aligned.m16n8k16.row.col.f32.f16.f16.f32 "
        "{%0,%1,%2,%3}, {%4,%5,%6,%7}, {%8,%9}, {%0,%1,%2,%3};\n"
        : "+f"(c[0]), "+f"(c[1]), "+f"(c[2]), "+f"(c[3])
        : "r"(a[0]), "r"(a[1]), "r"(a[2]), "r"(a[3]), "r"(b[0]), "r"(b[1]));
}
__device__ __forceinline__ uint32_t pack_h2(float x, float y) {
    __half2 h = __floats2half2_rn(x, y);
    return reinterpret_cast<uint32_t&>(h);
}

// ---------------------------------------------------------------------------
// Kernel 1: dinv[row] = rsqrt(rowsum(A)+1)  AND  g_Ah = fp16(A + I)  (fused)
//   The +I is folded into the fp16 store (diagonal element += 1).
// ---------------------------------------------------------------------------
__global__ void __launch_bounds__(256) deg_kernel(const float* __restrict__ A) {
    const int wid = threadIdx.x >> 5, lid = threadIdx.x & 31;
    const int row0 = blockIdx.x * 16 + wid * 2;
    const float4* r0 = reinterpret_cast<const float4*>(A + (size_t)row0 * NN);
    const float4* r1 = reinterpret_cast<const float4*>(A + (size_t)(row0 + 1) * NN);
    __half* h0 = g_Ah + (size_t)row0 * NN;
    __half* h1 = h0 + NN;
    const int d0col = row0 & (NN - 1);          // diagonal column (within batch)
    const int d1col = (row0 + 1) & (NN - 1);
    float s0 = 0.f, s1 = 0.f;
    #pragma unroll
    for (int i = 0; i < 8; i++) {
        const int c0 = (lid + i * 32) * 4;
        float4 a = r0[lid + i * 32];
        float4 b = r1[lid + i * 32];
        s0 += (a.x + a.y) + (a.z + a.w);
        s1 += (b.x + b.y) + (b.z + b.w);
        int da = d0col - c0, db = d1col - c0;
        if ((unsigned)da < 4u) (&a.x)[da] += 1.0f;   // fold +I
        if ((unsigned)db < 4u) (&b.x)[db] += 1.0f;
        uint2 pa = make_uint2(pack_h2(a.x, a.y), pack_h2(a.z, a.w));
        uint2 pb = make_uint2(pack_h2(b.x, b.y), pack_h2(b.z, b.w));
        *reinterpret_cast<uint2*>(h0 + c0) = pa;
        *reinterpret_cast<uint2*>(h1 + c0) = pb;
    }
    #pragma unroll
    for (int o = 16; o; o >>= 1) {
        s0 += __shfl_xor_sync(0xFFFFFFFFu, s0, o);
        s1 += __shfl_xor_sync(0xFFFFFFFFu, s1, o);
    }
    if (lid == 0) {
        g_dinv[row0]     = rsqrtf(s0 + 1.0f);
        g_dinv[row0 + 1] = rsqrtf(s1 + 1.0f);
    }
}

// ---------------------------------------------------------------------------
// Kernel 2: YsT_h[f][g] = fp16( d_m * (X @ W) )  via fp16 mma.sync.
//   (Ysn removed — identity is folded into Ah.)
// ---------------------------------------------------------------------------
#define P2 272
#define XS_SZ (128 * P2)
#define SMEM2 (2 * XS_SZ)

__global__ void __launch_bounds__(256) gemm_xw_t(const float* __restrict__ X,
                                                 const float* __restrict__ W) {
    extern __shared__ char sm2[];
    char* Xs = sm2;
    char* Ws = sm2 + XS_SZ;

    const int tid = threadIdx.x;
    const int wid = tid >> 5, lane = tid & 31;
    const int g = lane >> 2, tig = lane & 3;
    const int wm = wid & 1, wn = wid >> 1;
    const int m0g = blockIdx.x * 128;

    for (int idx = tid; idx < 128 * 128; idx += 256) {
        int k = idx >> 7, f = idx & 127;
        float w = W[idx];
        *reinterpret_cast<__half*>(Ws + f * P2 + k * 2) = __float2half_rn(w);
    }
    {
        const int r = tid >> 1, half = tid & 1;
        const float* xp = X + (size_t)(m0g + r) * FF + half * 64;
        char* dst = Xs + r * P2 + half * 128;
        #pragma unroll
        for (int j = 0; j < 8; j++) {
            float4 v0 = *reinterpret_cast<const float4*>(xp + j * 8);
            float4 v1 = *reinterpret_cast<const float4*>(xp + j * 8 + 4);
            uint4 o;
            o.x = pack_h2(v0.x, v0.y); o.y = pack_h2(v0.z, v0.w);
            o.z = pack_h2(v1.x, v1.y); o.w = pack_h2(v1.z, v1.w);
            *reinterpret_cast<uint4*>(dst + j * 16) = o;
        }
    }
    __syncthreads();

    float acc[4][4][4];
    #pragma unroll
    for (int i = 0; i < 4; i++)
        #pragma unroll
        for (int j = 0; j < 4; j++)
            #pragma unroll
            for (int k = 0; k < 4; k++) acc[i][j][k] = 0.f;

    #pragma unroll
    for (int ks = 0; ks < 8; ks++) {
        const int kb = ks * 32 + tig * 4;
        uint32_t af[4][4], bf2[4][2];
        #pragma unroll
        for (int mt = 0; mt < 4; mt++) {
            char* p = Xs + (wm * 64 + mt * 16 + g) * P2 + kb;
            af[mt][0] = *reinterpret_cast<uint32_t*>(p);
            af[mt][1] = *reinterpret_cast<uint32_t*>(p + 8 * P2);
            af[mt][2] = *reinterpret_cast<uint32_t*>(p + 16);
            af[mt][3] = *reinterpret_cast<uint32_t*>(p + 8 * P2 + 16);
        }
        #pragma unroll
        for (int nt = 0; nt < 4; nt++) {
            char* p = Ws + (wn * 32 + nt * 8 + g) * P2 + kb;
            bf2[nt][0] = *reinterpret_cast<uint32_t*>(p);
            bf2[nt][1] = *reinterpret_cast<uint32_t*>(p + 16);
        }
        #pragma unroll
        for (int mt = 0; mt < 4; mt++)
            #pragma unroll
            for (int nt = 0; nt < 4; nt++)
                mma_f16(acc[mt][nt], af[mt], bf2[nt]);
    }
    __syncthreads();

    // Stage transposed fp16 output Os[f][g] for coalesced YsT_h writes
    char* Os = Xs;
    #pragma unroll
    for (int mt = 0; mt < 4; mt++) {
        const int gl0 = wm * 64 + mt * 16 + g;
        const int gg0 = m0g + gl0;
        const float d0 = g_dinv[gg0];
        const float d1 = g_dinv[gg0 + 8];
        #pragma unroll
        for (int nt = 0; nt < 4; nt++) {
            const int f = wn * 32 + nt * 8 + tig * 2;
            float c0 = acc[mt][nt][0] * d0, c1 = acc[mt][nt][1] * d0;
            float c2 = acc[mt][nt][2] * d1, c3 = acc[mt][nt][3] * d1;
            *reinterpret_cast<__half*>(Os + f * P2 + gl0 * 2)             = __float2half_rn(c0);
            *reinterpret_cast<__half*>(Os + (f + 1) * P2 + gl0 * 2)       = __float2half_rn(c1);
            *reinterpret_cast<__half*>(Os + f * P2 + (gl0 + 8) * 2)       = __float2half_rn(c2);
            *reinterpret_cast<__half*>(Os + (f + 1) * P2 + (gl0 + 8) * 2) = __float2half_rn(c3);
        }
    }
    __syncthreads();
    {
        const int f = tid >> 1, half = tid & 1;
        char* src = Os + f * P2 + half * 128;
        __half* dst = g_YsT_h + (size_t)f * GTOT + m0g + half * 64;
        #pragma unroll
        for (int j = 0; j < 8; j++)
            *reinterpret_cast<uint4*>(dst + j * 8) = *reinterpret_cast<uint4*>(src + j * 16);
    }
}

// ---------------------------------------------------------------------------
// Kernel 3: out[b,n,:] = d_n * ( (A+I)[b,n,:] @ Ysd[b] )
//   fp16 ldmatrix + mma.sync, fp32 accum.  CTA 128x128, K-chunk 128,
//   3-stage cp.async pipeline (8 chunks, 8 syncs).
// ---------------------------------------------------------------------------
#define PA3 272                     // 128 fp16 = 256B + 16B pad (stride ≡ 4 banks)
#define TA3 (128 * PA3)             // 34816
#define STG3 (2 * TA3)              // 69632 (A + B per stage)
#define NSTAGE 3
#define SMEM3 (NSTAGE * STG3)       // 208896
#define NCHUNK (NN / 128)           // 8

__global__ void __launch_bounds__(256, 1) gemm_mma(float* __restrict__ out) {
    extern __shared__ char sm[];
    const uint32_t sb = smem_to_u32(sm);

    const int tid = threadIdx.x;
    const int wid = tid >> 5, lane = tid & 31;
    const int g = lane >> 2, tig = lane & 3;
    const int wm = wid & 1, wn = wid >> 1;
    const int b = blockIdx.y;
    const int rowStart = blockIdx.x * 128;

    // cp.async mapping: row = tid>>1, half = tid&1 covers 128B (64 halves)
    const int cr = tid >> 1;
    const int ch = tid & 1;
    const __half* Ap = g_Ah + ((size_t)b * NN + rowStart + cr) * NN + ch * 64;
    const __half* Bp = g_YsT_h + (size_t)cr * GTOT + (size_t)b * NN + ch * 64;
    const uint32_t dA0 = sb + cr * PA3 + ch * 128;
    const uint32_t dB0 = dA0 + TA3;

    auto issue = [&](int kc) {
        const uint32_t s = (kc % NSTAGE) * STG3;
        const __half* pa = Ap + kc * 128;
        const __half* pb = Bp + kc * 128;
        #pragma unroll
        for (int j = 0; j < 8; j++) CP_ASYNC_16(dA0 + s + j * 16, pa + j * 8);
        #pragma unroll
        for (int j = 0; j < 8; j++) CP_ASYNC_16(dB0 + s + j * 16, pb + j * 8);
        CP_ASYNC_COMMIT();
    };

    // ldmatrix lane addressing
    const int t = lane >> 3, r8 = lane & 7;
    // A x4 tiles: (m0,k0),(m0+8,k0),(m0,k0+8),(m0+8,k0+8)
    const uint32_t aOff = (uint32_t)(wm * 64 + (t & 1) * 8 + r8) * PA3 + ((t >> 1) * 8) * 2;
    // B x4 tiles (n-pair): (n0,k0),(n0,k0+8),(n0+8,k0),(n0+8,k0+8)
    const uint32_t bOff = TA3 + (uint32_t)(wn * 32 + (t >> 1) * 8 + r8) * PA3 + ((t & 1) * 8) * 2;

    float acc[4][4][4];
    #pragma unroll
    for (int i = 0; i < 4; i++)
        #pragma unroll
        for (int j = 0; j < 4; j++)
            #pragma unroll
            for (int k = 0; k < 4; k++) acc[i][j][k] = 0.f;

    issue(0);
    issue(1);

    for (int kc = 0; kc < NCHUNK; kc++) {
        if (kc < NCHUNK - 1) { CP_ASYNC_WAIT1(); } else { CP_ASYNC_WAIT0(); }
        __syncthreads();
        if (kc + 2 < NCHUNK) issue(kc + 2);

        const uint32_t st = sb + (kc % NSTAGE) * STG3;

        #pragma unroll
        for (int ks = 0; ks < 8; ks++) {
            uint32_t af[4][4], bf2[4][2];
            #pragma unroll
            for (int mt = 0; mt < 4; mt++)
                LDSM_X4(af[mt][0], af[mt][1], af[mt][2], af[mt][3],
                        st + aOff + (uint32_t)mt * 16 * PA3 + ks * 32);
            #pragma unroll
            for (int np = 0; np < 2; np++)
                LDSM_X4(bf2[np * 2][0], bf2[np * 2][1], bf2[np * 2 + 1][0], bf2[np * 2 + 1][1],
                        st + bOff + (uint32_t)np * 16 * PA3 + ks * 32);
            #pragma unroll
            for (int mt = 0; mt < 4; mt++)
                #pragma unroll
                for (int nt = 0; nt < 4; nt++)
                    mma_f16(acc[mt][nt], af[mt], bf2[nt]);
        }
    }

    // Epilogue: out = d_n * acc   (identity already inside A+I)
    #pragma unroll
    for (int mt = 0; mt < 4; mt++) {
        const int gr0 = b * NN + rowStart + wm * 64 + mt * 16 + g;
        const float d0 = g_dinv[gr0];
        const float d1 = g_dinv[gr0 + 8];
        float* o0 = out + (size_t)gr0 * FF + wn * 32 + tig * 2;
        float* o1 = o0 + (size_t)8 * FF;
        #pragma unroll
        for (int nt = 0; nt < 4; nt++) {
            float2 v0, v1;
            v0.x = d0 * acc[mt][nt][0];
            v0.y = d0 * acc[mt][nt][1];
            v1.x = d1 * acc[mt][nt][2];
            v1.y = d1 * acc[mt][nt][3];
            *reinterpret_cast<float2*>(o0 + nt * 8) = v0;
            *reinterpret_cast<float2*>(o1 + nt * 8) = v1;
        }
    }
}

// ---------------------------------------------------------------------------
// kernel_launch
// ---------------------------------------------------------------------------
extern "C" void kernel_launch(void* const* d_in, const int* in_sizes, int n_in,
                              void* d_out, int out_size) {
    const float* X = (const float*)d_in[0];   // [16,1024,128]
    const float* A = (const float*)d_in[1];   // [16,1024,1024]
    const float* W = (const float*)d_in[2];   // [128,128]
    float* out = (float*)d_out;               // [16,1024,128]

    cudaFuncSetAttribute(gemm_xw_t, cudaFuncAttributeMaxDynamicSharedMemorySize, SMEM2);
    cudaFuncSetAttribute(gemm_mma, cudaFuncAttributeMaxDynamicSharedMemorySize, SMEM3);

    // 1) dinv = rsqrt(rowsum(A)+1)  +  Ah = fp16(A + I) (fused)
    deg_kernel<<<GTOT / 16, 256>>>(A);

    // 2) YsT_h = fp16(d_m * (X @ W)), transposed
    gemm_xw_t<<<GTOT / 128, 256, SMEM2>>>(X, W);

    // 3) out = d_n * ((A+I) @ Ysd)  via ldmatrix + fp16 mma.sync
    {
        dim3 grid(NN / 128, BATCH);
        gemm_mma<<<grid, 256, SMEM3>>>(out);
    }
}

// round 11
// speedup vs baseline: 1.2026x; 1.0949x over previous
#include <cuda_runtime.h>
#include <cuda_fp16.h>
#include <cstdint>

// Problem constants
#define BATCH 16
#define NN    1024
#define FF    128
#define GTOT  (BATCH * NN)     // 16384

// ---------------------------------------------------------------------------
// Device-global scratch (no allocations allowed)
// ---------------------------------------------------------------------------
__device__ float  g_dinv[GTOT];             // 64 KB
__device__ __half g_Ah[(size_t)GTOT * NN];  // 32 MB  (A, diag patched to A+1) fp16
__device__ __half g_YsT_h[FF * GTOT];       // 4 MB   [f][g] fp16, d_m-scaled

// ---------------------------------------------------------------------------
// Helpers
// ---------------------------------------------------------------------------
__device__ __forceinline__ uint32_t smem_to_u32(const void* p) {
    uint32_t a;
    asm("{ .reg .u64 t; cvta.to.shared.u64 t, %1; cvt.u32.u64 %0, t; }" : "=r"(a) : "l"(p));
    return a;
}
#define CP_ASYNC_16(dst_u32, src) \
    asm volatile("cp.async.cg.shared.global [%0], [%1], 16;" \
                 :: "r"(dst_u32), "l"(src) : "memory")
#define CP_ASYNC_COMMIT()  asm volatile("cp.async.commit_group;" ::: "memory")
#define CP_ASYNC_WAIT1()   asm volatile("cp.async.wait_group 1;" ::: "memory")
#define CP_ASYNC_WAIT0()   asm volatile("cp.async.wait_group 0;" ::: "memory")

#define LDSM_X4(r0, r1, r2, r3, addr) \
    asm volatile("ldmatrix.sync.aligned.m8n8.x4.shared.b16 {%0,%1,%2,%3}, [%4];" \
                 : "=r"(r0), "=r"(r1), "=r"(r2), "=r"(r3) : "r"(addr))

__device__ __forceinline__ void mma_f16(float* c, const uint32_t* a, const uint32_t* b) {
    asm volatile(
        "mma.sync.aligned.m16n8k16.row.col.f32.f16.f16.f32 "
        "{%0,%1,%2,%3}, {%4,%5,%6,%7}, {%8,%9}, {%0,%1,%2,%3};\n"
        : "+f"(c[0]), "+f"(c[1]), "+f"(c[2]), "+f"(c[3])
        : "r"(a[0]), "r"(a[1]), "r"(a[2]), "r"(a[3]), "r"(b[0]), "r"(b[1]));
}
__device__ __forceinline__ uint32_t pack_h2(float x, float y) {
    __half2 h = __floats2half2_rn(x, y);
    return reinterpret_cast<uint32_t&>(h);
}

// ---------------------------------------------------------------------------
// Kernel 1: dinv[row] = rsqrt(rowsum(A)+1)  AND  g_Ah = fp16(A)   (R8 version)
// ---------------------------------------------------------------------------
__global__ void __launch_bounds__(256) deg_kernel(const float* __restrict__ A) {
    const int wid = threadIdx.x >> 5, lid = threadIdx.x & 31;
    const int row0 = blockIdx.x * 16 + wid * 2;
    const float4* r0 = reinterpret_cast<const float4*>(A + (size_t)row0 * NN);
    const float4* r1 = reinterpret_cast<const float4*>(A + (size_t)(row0 + 1) * NN);
    __half* h0 = g_Ah + (size_t)row0 * NN;
    __half* h1 = h0 + NN;
    float s0 = 0.f, s1 = 0.f;
    #pragma unroll
    for (int i = 0; i < 8; i++) {
        float4 a = r0[lid + i * 32];
        float4 b = r1[lid + i * 32];
        s0 += (a.x + a.y) + (a.z + a.w);
        s1 += (b.x + b.y) + (b.z + b.w);
        uint2 pa = make_uint2(pack_h2(a.x, a.y), pack_h2(a.z, a.w));
        uint2 pb = make_uint2(pack_h2(b.x, b.y), pack_h2(b.z, b.w));
        *reinterpret_cast<uint2*>(h0 + (lid + i * 32) * 4) = pa;
        *reinterpret_cast<uint2*>(h1 + (lid + i * 32) * 4) = pb;
    }
    #pragma unroll
    for (int o = 16; o; o >>= 1) {
        s0 += __shfl_xor_sync(0xFFFFFFFFu, s0, o);
        s1 += __shfl_xor_sync(0xFFFFFFFFu, s1, o);
    }
    if (lid == 0) {
        g_dinv[row0]     = rsqrtf(s0 + 1.0f);
        g_dinv[row0 + 1] = rsqrtf(s1 + 1.0f);
    }
}

// ---------------------------------------------------------------------------
// Kernel 2: YsT_h[f][g] = fp16( d_m * (X @ W) )  via fp16 mma.sync,
//   PLUS diagonal patch: g_Ah[g][g%N] = fp16(A[g][g%N] + 1).
// ---------------------------------------------------------------------------
#define P2 272
#define XS_SZ (128 * P2)
#define SMEM2 (2 * XS_SZ)

__global__ void __launch_bounds__(256) gemm_xw_t(const float* __restrict__ X,
                                                 const float* __restrict__ W,
                                                 const float* __restrict__ A) {
    extern __shared__ char sm2[];
    char* Xs = sm2;
    char* Ws = sm2 + XS_SZ;

    const int tid = threadIdx.x;
    const int wid = tid >> 5, lane = tid & 31;
    const int g = lane >> 2, tig = lane & 3;
    const int wm = wid & 1, wn = wid >> 1;
    const int m0g = blockIdx.x * 128;

    // Diagonal patch for this block's 128 rows (A+I folded into Ah)
    if (tid < 128) {
        const int gr = m0g + tid;
        const int dc = gr & (NN - 1);
        const size_t idx = (size_t)gr * NN + dc;
        g_Ah[idx] = __float2half_rn(A[idx] + 1.0f);
    }

    for (int idx = tid; idx < 128 * 128; idx += 256) {
        int k = idx >> 7, f = idx & 127;
        float w = W[idx];
        *reinterpret_cast<__half*>(Ws + f * P2 + k * 2) = __float2half_rn(w);
    }
    {
        const int r = tid >> 1, half = tid & 1;
        const float* xp = X + (size_t)(m0g + r) * FF + half * 64;
        char* dst = Xs + r * P2 + half * 128;
        #pragma unroll
        for (int j = 0; j < 8; j++) {
            float4 v0 = *reinterpret_cast<const float4*>(xp + j * 8);
            float4 v1 = *reinterpret_cast<const float4*>(xp + j * 8 + 4);
            uint4 o;
            o.x = pack_h2(v0.x, v0.y); o.y = pack_h2(v0.z, v0.w);
            o.z = pack_h2(v1.x, v1.y); o.w = pack_h2(v1.z, v1.w);
            *reinterpret_cast<uint4*>(dst + j * 16) = o;
        }
    }
    __syncthreads();

    float acc[4][4][4];
    #pragma unroll
    for (int i = 0; i < 4; i++)
        #pragma unroll
        for (int j = 0; j < 4; j++)
            #pragma unroll
            for (int k = 0; k < 4; k++) acc[i][j][k] = 0.f;

    #pragma unroll
    for (int ks = 0; ks < 8; ks++) {
        const int kb = ks * 32 + tig * 4;
        uint32_t af[4][4], bf2[4][2];
        #pragma unroll
        for (int mt = 0; mt < 4; mt++) {
            char* p = Xs + (wm * 64 + mt * 16 + g) * P2 + kb;
            af[mt][0] = *reinterpret_cast<uint32_t*>(p);
            af[mt][1] = *reinterpret_cast<uint32_t*>(p + 8 * P2);
            af[mt][2] = *reinterpret_cast<uint32_t*>(p + 16);
            af[mt][3] = *reinterpret_cast<uint32_t*>(p + 8 * P2 + 16);
        }
        #pragma unroll
        for (int nt = 0; nt < 4; nt++) {
            char* p = Ws + (wn * 32 + nt * 8 + g) * P2 + kb;
            bf2[nt][0] = *reinterpret_cast<uint32_t*>(p);
            bf2[nt][1] = *reinterpret_cast<uint32_t*>(p + 16);
        }
        #pragma unroll
        for (int mt = 0; mt < 4; mt++)
            #pragma unroll
            for (int nt = 0; nt < 4; nt++)
                mma_f16(acc[mt][nt], af[mt], bf2[nt]);
    }
    __syncthreads();

    // Stage transposed fp16 output Os[f][g] for coalesced YsT_h writes
    char* Os = Xs;
    #pragma unroll
    for (int mt = 0; mt < 4; mt++) {
        const int gl0 = wm * 64 + mt * 16 + g;
        const int gg0 = m0g + gl0;
        const float d0 = g_dinv[gg0];
        const float d1 = g_dinv[gg0 + 8];
        #pragma unroll
        for (int nt = 0; nt < 4; nt++) {
            const int f = wn * 32 + nt * 8 + tig * 2;
            float c0 = acc[mt][nt][0] * d0, c1 = acc[mt][nt][1] * d0;
            float c2 = acc[mt][nt][2] * d1, c3 = acc[mt][nt][3] * d1;
            *reinterpret_cast<__half*>(Os + f * P2 + gl0 * 2)             = __float2half_rn(c0);
            *reinterpret_cast<__half*>(Os + (f + 1) * P2 + gl0 * 2)       = __float2half_rn(c1);
            *reinterpret_cast<__half*>(Os + f * P2 + (gl0 + 8) * 2)       = __float2half_rn(c2);
            *reinterpret_cast<__half*>(Os + (f + 1) * P2 + (gl0 + 8) * 2) = __float2half_rn(c3);
        }
    }
    __syncthreads();
    {
        const int f = tid >> 1, half = tid & 1;
        char* src = Os + f * P2 + half * 128;
        __half* dst = g_YsT_h + (size_t)f * GTOT + m0g + half * 64;
        #pragma unroll
        for (int j = 0; j < 8; j++)
            *reinterpret_cast<uint4*>(dst + j * 8) = *reinterpret_cast<uint4*>(src + j * 16);
    }
}

// ---------------------------------------------------------------------------
// Kernel 3: out[b,n,:] = d_n * ( (A+I)[b,n,:] @ Ysd[b] )
//   R8 structure: CTA 128x128, K-chunk 64, 3-stage cp.async, ldmatrix + fp16
//   mma.sync — with the Ysn-free epilogue (identity lives in Ah's diagonal).
// ---------------------------------------------------------------------------
#define PA3 144                     // 64 fp16 = 128B + 16B pad
#define TA3 (128 * PA3)             // 18432
#define STG3 (2 * TA3)              // 36864 (A + B per stage)
#define NSTAGE 3
#define SMEM3 (NSTAGE * STG3)       // 110592
#define NCHUNK (NN / 64)            // 16

__global__ void __launch_bounds__(256, 1) gemm_mma(float* __restrict__ out) {
    extern __shared__ char sm[];
    const uint32_t sb = smem_to_u32(sm);

    const int tid = threadIdx.x;
    const int wid = tid >> 5, lane = tid & 31;
    const int g = lane >> 2, tig = lane & 3;
    const int wm = wid & 1, wn = wid >> 1;
    const int b = blockIdx.y;
    const int rowStart = blockIdx.x * 128;

    // cp.async mapping: row = tid>>1, half = tid&1 (32 of 64 k-values, 64B)
    const int cr = tid >> 1;
    const int ch = tid & 1;
    const __half* Ap = g_Ah + ((size_t)b * NN + rowStart + cr) * NN + ch * 32;
    const __half* Bp = g_YsT_h + (size_t)cr * GTOT + (size_t)b * NN + ch * 32;
    const uint32_t dA0 = sb + cr * PA3 + ch * 64;
    const uint32_t dB0 = dA0 + TA3;

    auto issue = [&](int kc) {
        const uint32_t s = (kc % NSTAGE) * STG3;
        const __half* pa = Ap + kc * 64;
        const __half* pb = Bp + kc * 64;
        #pragma unroll
        for (int j = 0; j < 4; j++) CP_ASYNC_16(dA0 + s + j * 16, pa + j * 8);
        #pragma unroll
        for (int j = 0; j < 4; j++) CP_ASYNC_16(dB0 + s + j * 16, pb + j * 8);
        CP_ASYNC_COMMIT();
    };

    // ldmatrix lane addressing
    const int t = lane >> 3, r8 = lane & 7;
    const uint32_t aOff = (uint32_t)(wm * 64 + (t & 1) * 8 + r8) * PA3 + ((t >> 1) * 8) * 2;
    const uint32_t bOff = TA3 + (uint32_t)(wn * 32 + (t >> 1) * 8 + r8) * PA3 + ((t & 1) * 8) * 2;

    float acc[4][4][4];
    #pragma unroll
    for (int i = 0; i < 4; i++)
        #pragma unroll
        for (int j = 0; j < 4; j++)
            #pragma unroll
            for (int k = 0; k < 4; k++) acc[i][j][k] = 0.f;

    issue(0);
    issue(1);

    for (int kc = 0; kc < NCHUNK; kc++) {
        if (kc < NCHUNK - 1) { CP_ASYNC_WAIT1(); } else { CP_ASYNC_WAIT0(); }
        __syncthreads();
        if (kc + 2 < NCHUNK) issue(kc + 2);

        const uint32_t st = sb + (kc % NSTAGE) * STG3;

        #pragma unroll
        for (int ks = 0; ks < 4; ks++) {
            uint32_t af[4][4], bf2[4][2];
            #pragma unroll
            for (int mt = 0; mt < 4; mt++)
                LDSM_X4(af[mt][0], af[mt][1], af[mt][2], af[mt][3],
                        st + aOff + (uint32_t)mt * 16 * PA3 + ks * 32);
            #pragma unroll
            for (int np = 0; np < 2; np++)
                LDSM_X4(bf2[np * 2][0], bf2[np * 2][1], bf2[np * 2 + 1][0], bf2[np * 2 + 1][1],
                        st + bOff + (uint32_t)np * 16 * PA3 + ks * 32);
            #pragma unroll
            for (int mt = 0; mt < 4; mt++)
                #pragma unroll
                for (int nt = 0; nt < 4; nt++)
                    mma_f16(acc[mt][nt], af[mt], bf2[nt]);
        }
    }

    // Epilogue: out = d_n * acc   (identity already inside A+I)
    #pragma unroll
    for (int mt = 0; mt < 4; mt++) {
        const int gr0 = b * NN + rowStart + wm * 64 + mt * 16 + g;
        const float d0 = g_dinv[gr0];
        const float d1 = g_dinv[gr0 + 8];
        float* o0 = out + (size_t)gr0 * FF + wn * 32 + tig * 2;
        float* o1 = o0 + (size_t)8 * FF;
        #pragma unroll
        for (int nt = 0; nt < 4; nt++) {
            float2 v0, v1;
            v0.x = d0 * acc[mt][nt][0];
            v0.y = d0 * acc[mt][nt][1];
            v1.x = d1 * acc[mt][nt][2];
            v1.y = d1 * acc[mt][nt][3];
            *reinterpret_cast<float2*>(o0 + nt * 8) = v0;
            *reinterpret_cast<float2*>(o1 + nt * 8) = v1;
        }
    }
}

// ---------------------------------------------------------------------------
// kernel_launch
// ---------------------------------------------------------------------------
extern "C" void kernel_launch(void* const* d_in, const int* in_sizes, int n_in,
                              void* d_out, int out_size) {
    const float* X = (const float*)d_in[0];   // [16,1024,128]
    const float* A = (const float*)d_in[1];   // [16,1024,1024]
    const float* W = (const float*)d_in[2];   // [128,128]
    float* out = (float*)d_out;               // [16,1024,128]

    cudaFuncSetAttribute(gemm_xw_t, cudaFuncAttributeMaxDynamicSharedMemorySize, SMEM2);
    cudaFuncSetAttribute(gemm_mma, cudaFuncAttributeMaxDynamicSharedMemorySize, SMEM3);

    // 1) dinv = rsqrt(rowsum(A)+1)  +  Ah = fp16(A) (fused, branch-free)
    deg_kernel<<<GTOT / 16, 256>>>(A);

    // 2) YsT_h = fp16(d_m * (X @ W)) transposed  +  Ah diagonal patch (+I)
    gemm_xw_t<<<GTOT / 128, 256, SMEM2>>>(X, W, A);

    // 3) out = d_n * ((A+I) @ Ysd)  via ldmatrix + fp16 mma.sync
    {
        dim3 grid(NN / 128, BATCH);
        gemm_mma<<<grid, 256, SMEM3>>>(out);
    }
}